// round 15
// baseline (speedup 1.0000x reference)
#include <cuda_runtime.h>
#include <cstdint>

#define Nn   2048
#define Ee   65536
#define INC  128
#define HIDc 32
#define LATc 16
#define DECB 512

typedef unsigned long long ull;

// ---------------- scratch (static zero; self-cleaning each run) ----------------
__device__ float g_deg [Nn];                       // edge count; reset in dec phase A
__device__ __align__(16) float g_xw  [Nn*HIDc];
__device__ __align__(16) float g_agg1[Nn*HIDc];   // reset in dec phase A
__device__ __align__(16) float g_aggh[Nn*HIDc];   // reset in dec phase A
__device__ __align__(16) float g_hi  [Nn*LATc];
__device__ __align__(16) float g_hjT [LATc*Nn];   // transposed: [l][i]

__device__ unsigned          g_bar_arr;            // self-resetting
__device__ volatile unsigned g_bar_rel;            // monotonic

// ---------------- helpers ----------------
__device__ __forceinline__ void pdl_trigger() {
    asm volatile("griddepcontrol.launch_dependents;");
}
__device__ __forceinline__ void pdl_wait() {
    asm volatile("griddepcontrol.wait;" ::: "memory");
}
__device__ __forceinline__ int eidx(const void* p, int pos, int is64) {
    if (is64) return (int)((const long long*)p)[pos];
    return ((const int*)p)[pos];
}
__device__ __forceinline__ int detect64(const void* p_) {
    const ull* p = (const ull*)p_;
    ull orv = 0;
#pragma unroll
    for (int k = 0; k < 64; k++) orv |= p[k];
    return ((orv >> 32) == 0ull) ? 1 : 0;
}
__device__ __forceinline__ void red4(float* addr, float4 v) {
    asm volatile("red.global.add.v4.f32 [%0], {%1, %2, %3, %4};"
                 :: "l"(__cvta_generic_to_global(addr)),
                    "f"(v.x), "f"(v.y), "f"(v.z), "f"(v.w) : "memory");
}
__device__ __forceinline__ ull f32x2_add(ull a, ull b) {
    ull r; asm("add.rn.f32x2 %0, %1, %2;" : "=l"(r) : "l"(a), "l"(b)); return r;
}
__device__ __forceinline__ ull f32x2_fma(ull a, ull b, ull c) {
    ull r; asm("fma.rn.f32x2 %0, %1, %2, %3;" : "=l"(r) : "l"(a), "l"(b), "l"(c)); return r;
}
__device__ __forceinline__ ull pack2(float lo, float hi) {
    ull r; asm("mov.b64 %0, {%1, %2};" : "=l"(r) : "f"(lo), "f"(hi)); return r;
}
__device__ __forceinline__ float2 unpack2(ull v) {
    float2 f; asm("mov.b64 {%0, %1}, %2;" : "=f"(f.x), "=f"(f.y) : "l"(v)); return f;
}
__device__ __forceinline__ float fast_sigmoid(float x) {
    float t;
    asm("tanh.approx.f32 %0, %1;" : "=f"(t) : "f"(0.5f * x));
    return fmaf(0.5f, t, 0.5f);
}
// grid barrier for DECB co-resident blocks (launch_bounds(256,4) => capacity 592 >= 512)
__device__ __forceinline__ void dbar() {
    __syncthreads();
    if (threadIdx.x == 0) {
        unsigned before = g_bar_rel;
        __threadfence();
        if (atomicAdd(&g_bar_arr, 1u) == DECB - 1) {
            g_bar_arr = 0;                         // self-reset for next replay
            __threadfence();
            atomicAdd((unsigned*)&g_bar_rel, 1u);
        } else {
            while (g_bar_rel == before) __nanosleep(32);
            __threadfence();
        }
    }
    __syncthreads();
}

// ---------------- kernels ----------------

// L1: deg atomics | xw = x @ W1 (8 rows/block) | zero adj_true
__global__ void k_pre(const void* __restrict__ ei,
                      const float* __restrict__ x, const float* __restrict__ W1,
                      float4* __restrict__ adjt4) {
    __shared__ float xs[8][INC];
    __shared__ int   s64;
    int tid = threadIdx.x;
    int t   = blockIdx.x * 256 + tid;                 // 0..65535
    if (tid == 0) { pdl_trigger(); s64 = detect64(ei); }
#pragma unroll
    for (int k = 0; k < 16; k++)
        adjt4[t + k * 65536] = make_float4(0.f, 0.f, 0.f, 0.f);
    for (int u = tid; u < 8 * INC; u += 256) {
        int r = u / INC, k = u % INC;
        xs[r][k] = x[(blockIdx.x * 8 + r) * INC + k];
    }
    __syncthreads();
    atomicAdd(&g_deg[eidx(ei, Ee + t, s64)], 1.0f);
    int row = blockIdx.x * 8 + (tid >> 5);
    int c   = tid & 31;
    float s = 0.f;
#pragma unroll 8
    for (int k = 0; k < INC; k++) s = fmaf(xs[tid >> 5][k], W1[k * HIDc + c], s);
    g_xw[row * HIDc + c] = s;
}

// L2: eagg1 (8 threads/edge, 1 red4 each) | adj_true scatter
__global__ void k_eagg1true(const void* __restrict__ ei,
                            const void* __restrict__ eit, float* __restrict__ adjt) {
    __shared__ int s64, s64t;
    int tx = threadIdx.x;
    if (tx == 0)  { pdl_trigger(); s64 = detect64(ei); }
    if (tx == 32) s64t = detect64(eit);
    __syncthreads();
    int t = blockIdx.x * 256 + tx;                    // 524288 threads
    int e = t >> 3, c = t & 7;
    int s = eidx(ei, e, s64), d = eidx(ei, Ee + e, s64);
    int ti = eidx(eit, e, s64t), tj = eidx(eit, Ee + e, s64t);
    pdl_wait();
    if (c == 0) atomicAdd(&adjt[ti * Nn + tj], 1.0f);
    float nw = rsqrtf((g_deg[s] + 1.0f) * (g_deg[d] + 1.0f));
    float4 a = ((const float4*)g_xw)[s * 8 + c];
    a.x *= nw; a.y *= nw; a.z *= nw; a.w *= nw;
    red4(&g_agg1[d * HIDc + c * 4], a);
}

// L3: eagg2 with h1 computed inline per edge
__global__ void k_eagg2(const void* __restrict__ ei, const float* __restrict__ b1) {
    __shared__ int s64;
    if (threadIdx.x == 0) { pdl_trigger(); s64 = detect64(ei); }
    __syncthreads();
    int t = blockIdx.x * 256 + threadIdx.x;           // 524288 threads
    int e = t >> 3, c = t & 7;
    int s = eidx(ei, e, s64), d = eidx(ei, Ee + e, s64);
    float4 bb = ((const float4*)b1)[c];
    pdl_wait();
    float ds = g_deg[s];
    float nw = rsqrtf((ds + 1.0f) * (g_deg[d] + 1.0f));
    float d2 = 1.0f / (ds + 1.0f);
    float4 a  = ((const float4*)g_agg1)[s * 8 + c];
    float4 xx = ((const float4*)g_xw)[s * 8 + c];
    float4 h;
    h.x = nw * fmaxf(fmaf(d2, xx.x, a.x) + bb.x, 0.f);
    h.y = nw * fmaxf(fmaf(d2, xx.y, a.y) + bb.y, 0.f);
    h.z = nw * fmaxf(fmaf(d2, xx.z, a.z) + bb.z, 0.f);
    h.w = nw * fmaxf(fmaf(d2, xx.w, a.w) + bb.w, 0.f);
    red4(&g_aggh[d * HIDc + c * 4], h);
}

// L4: [phase A: zhij (warp/node) | barrier | phase B: decoder, 2 tiles/block]
__global__ void __launch_bounds__(256, 4)
k_dec(const float* __restrict__ b1,
      const float* __restrict__ Wmu, const float* __restrict__ bmu,
      const float* __restrict__ Wlv, const float* __restrict__ blv,
      const float* __restrict__ eps,
      const float* __restrict__ dW1, const float* __restrict__ db1,
      const float* __restrict__ dW2, const float* __restrict__ db2,
      float* __restrict__ out_mu, float* __restrict__ out_lv,
      float* __restrict__ adj) {
    __shared__ ull   hisp[8][16];                     // (h,h) packed pairs
    __shared__ ull   s_w2h[LATc];                     // (w/2, w/2) packed
    __shared__ float s_b2;
    int tx = threadIdx.x;
    // prologue: weights (independent of predecessors)
    if (tx < LATc) { float wh = 0.5f * dW2[tx]; s_w2h[tx] = pack2(wh, wh); }
    if (tx == LATc) s_b2 = db2[0];

    pdl_wait();

    // ===== phase A: zhij — warp per node (warps 0..2047) =====
    {
        int gw   = blockIdx.x * 8 + (tx >> 5);        // global warp id, 4096 warps
        int lane = tx & 31;
        int l    = lane & 15;
        if (gw < Nn) {
            int i = gw;
            float bias1 = b1[lane];
            float bmlv  = (lane < 16) ? bmu[l] : blv[l];
            float ev    = eps[i * LATc + l];
            float dbv   = (lane < 16) ? db1[l] : 0.f;
            float deg = g_deg[i];
            float d2  = 1.0f / (deg + 1.0f);
            int idx = i * HIDc + lane;
            float aggh = g_aggh[idx];
            float h1 = fmaxf(fmaf(d2, g_xw[idx], g_agg1[idx]) + bias1, 0.f);
            g_agg1[idx] = 0.f; g_aggh[idx] = 0.f;     // reset for next replay
            if (lane == 0) g_deg[i] = 0.f;
            float v = fmaf(d2, h1, aggh);

            const float* W  = (lane < 16) ? Wmu : Wlv;
            float acc = bmlv;
#pragma unroll
            for (int k = 0; k < HIDc; k++)
                acc = fmaf(__shfl_sync(0xffffffffu, v, k), W[k * LATc + l], acc);
            if (lane < 16) out_mu[i * LATc + l] = acc;
            else           out_lv[i * LATc + l] = acc;

            float other = __shfl_xor_sync(0xffffffffu, acc, 16);
            float z = (lane < 16) ? fmaf(ev, __expf(0.5f * other), acc)
                                  : fmaf(ev, __expf(0.5f * acc), other);

            const float* DW = (lane < 16) ? dW1 : dW1 + LATc * LATc;
            float si = dbv;
#pragma unroll
            for (int k = 0; k < LATc; k++)
                si = fmaf(__shfl_sync(0xffffffffu, z, k), DW[k * LATc + l], si);
            if (lane < 16) g_hi[i * LATc + l] = si;
            else           g_hjT[l * Nn + i]  = si;
        }
    }

    dbar();                                           // grid barrier (512 co-resident blocks)

    // ===== phase B: decoder, 2 tiles (8 rows x 512 cols) per block =====
    const ull ABSMASK = 0x7FFFFFFF7FFFFFFFull;
    float b2 = s_b2;
    for (int t = blockIdx.x; t < 1024; t += DECB) {
        int it = t >> 2, jt = t & 3;
        int i0 = it * 8, j0 = jt * 512;
        __syncthreads();                              // protect hisp reuse
        if (tx < 128) {
            float h = g_hi[(i0 + (tx >> 4)) * LATc + (tx & 15)];
            hisp[tx >> 4][tx & 15] = pack2(h, h);
        }
        ull hjp[LATc];
#pragma unroll
        for (int l = 0; l < LATc; l++)
            hjp[l] = *(const ull*)&g_hjT[l * Nn + j0 + 2 * tx];
        __syncthreads();

        size_t obase = (size_t)i0 * Nn + j0 + 2 * tx;
#pragma unroll
        for (int r = 0; r < 8; r++) {
            ull acc = pack2(b2, b2);
#pragma unroll
            for (int l = 0; l < LATc; l++) {
                ull s = f32x2_add(hisp[r][l], hjp[l]);
                ull u = f32x2_add(s, s & ABSMASK);    // s + |s| == 2*relu(s) exactly
                acc = f32x2_fma(u, s_w2h[l], acc);    // * (w/2)
            }
            float2 sv = unpack2(acc);
            float2 o;
            o.x = fast_sigmoid(sv.x);
            o.y = fast_sigmoid(sv.y);
            *(float2*)&adj[obase + (size_t)r * Nn] = o;
        }
    }
}

// ---------------- launcher: 4 nodes chained with PDL ----------------
template <typename... Args>
static void launch_pdl(void (*kern)(Args...), dim3 grid, dim3 block, Args... args) {
    cudaLaunchConfig_t cfg = {};
    cfg.gridDim = grid; cfg.blockDim = block; cfg.stream = 0;
    cudaLaunchAttribute at[1];
    at[0].id = cudaLaunchAttributeProgrammaticStreamSerialization;
    at[0].val.programmaticStreamSerializationAllowed = 1;
    cfg.attrs = at; cfg.numAttrs = 1;
    if (cudaLaunchKernelEx(&cfg, kern, args...) != cudaSuccess) {
        void* pargs[] = { (void*)&args... };
        cudaLaunchKernel((const void*)kern, grid, block, pargs, 0, 0);
    }
}

extern "C" void kernel_launch(void* const* d_in, const int* in_sizes, int n_in,
                              void* d_out, int out_size) {
    const float* x    = (const float*)d_in[0];
    const float* eps  = (const float*)d_in[1];
    const float* W1   = (const float*)d_in[2];
    const float* b1   = (const float*)d_in[3];
    const float* Wmu  = (const float*)d_in[4];
    const float* bmu  = (const float*)d_in[5];
    const float* Wlv  = (const float*)d_in[6];
    const float* blv  = (const float*)d_in[7];
    const float* dW1  = (const float*)d_in[8];
    const float* db1  = (const float*)d_in[9];
    const float* dW2  = (const float*)d_in[10];
    const float* db2  = (const float*)d_in[11];
    const void*  ei   = d_in[12];
    const void*  eit  = d_in[13];

    float* out      = (float*)d_out;
    float* adj_pred = out;
    float* adj_true = out + (size_t)Nn * Nn;
    float* out_mu   = out + 2 * (size_t)Nn * Nn;
    float* out_lv   = out_mu + Nn * LATc;

    launch_pdl(k_pre,       dim3(256), dim3(256), ei, x, W1, (float4*)adj_true);
    launch_pdl(k_eagg1true, dim3(2048), dim3(256), ei, eit, adj_true);
    launch_pdl(k_eagg2,     dim3(2048), dim3(256), ei, b1);
    launch_pdl(k_dec,       dim3(DECB), dim3(256),
               b1, Wmu, bmu, Wlv, blv, eps, dW1, db1, dW2, db2,
               out_mu, out_lv, adj_pred);
}